// round 6
// baseline (speedup 1.0000x reference)
#include <cuda_runtime.h>
#include <math.h>

// Problem constants
#define BB 2048   // batch
#define DD 512    // hidden
#define CC 128    // vocab
#define TT 151    // steps
#define G3 1536   // 3*DD

// Persistent scratch (allowed: __device__ globals, no runtime allocation)
__device__ float g_h[2][BB * DD];          // ping-pong hidden state, 8 MB
__device__ float g_tab[(CC + 1) * G3];     // gi table: embed@W_ih^T + b_ih (+ b_hh r/z folded)
__device__ int   g_tok[BB];                // previous token per batch row

__device__ __forceinline__ float sigm(float x) { return 1.f / (1.f + expf(-x)); }

// Packed fp32x2 FMA (Blackwell FFMA2; only reachable via PTX fma.rn.f32x2)
#define FMA2(acc, a, b) \
    asm("fma.rn.f32x2 %0, %1, %2, %0;" : "+l"(acc) : "l"(a), "l"(b))

__device__ __forceinline__ float lo32(unsigned long long v) { return __uint_as_float((unsigned)v); }
__device__ __forceinline__ float hi32(unsigned long long v) { return __uint_as_float((unsigned)(v >> 32)); }

// ---------------------------------------------------------------------------
// Precompute gi table: g_tab[c][j] = embed[c]·W_ih[j] + b_ih[j] + (j<1024 ? b_hh[j] : 0)
// Row CC (=128) is the zero-input row (t=0): just the biases.
// grid (129, 6), 256 threads
// ---------------------------------------------------------------------------
__global__ void build_tab(const float* __restrict__ Wih, const float* __restrict__ bih,
                          const float* __restrict__ bhh, const float* __restrict__ embed) {
    __shared__ float se[DD];
    int c = blockIdx.x;                      // 0..128
    int j = blockIdx.y * 256 + threadIdx.x;  // 0..1535
    for (int i = threadIdx.x; i < DD; i += 256)
        se[i] = (c < CC) ? embed[c * DD + i] : 0.f;
    __syncthreads();
    float acc = bih[j] + (j < 2 * DD ? bhh[j] : 0.f);
    if (c < CC) {
        const float4* w  = (const float4*)(Wih + (size_t)j * DD);
        const float4* s4 = (const float4*)se;
        #pragma unroll 8
        for (int k = 0; k < DD / 4; k++) {
            float4 wv = w[k], sv = s4[k];
            acc += wv.x * sv.x;
            acc += wv.y * sv.y;
            acc += wv.z * sv.z;
            acc += wv.w * sv.w;
        }
    }
    g_tab[(size_t)c * G3 + j] = acc;
}

__global__ void init_tok() {
    int i = blockIdx.x * blockDim.x + threadIdx.x;
    if (i < BB) g_tok[i] = CC;  // zero-input table row
}

// ---------------------------------------------------------------------------
// Kernel 1: gh = h @ W_hh^T, fused gates + gi table lookup -> h_new
// grid (BB/64, DD/64) = (32, 8), 256 threads.
// Block tile: 64 batch rows x 64 hidden cols x 3 gates, K=512.
// A staged in SMEM as duplicated fp32 pairs so the inner loop is pure FFMA2.
// ---------------------------------------------------------------------------
__global__ __launch_bounds__(256, 2)
void step_h(const float* __restrict__ feat, const float* __restrict__ Whh,
            const float* __restrict__ bhh, int t) {
    __shared__ __align__(16) float2 As[16][66];     // [k][m], value duplicated in both lanes
    __shared__ __align__(16) float  Bs[3][16][68];  // [gate][k][n]

    const float* hin  = (t == 0) ? feat : g_h[(t - 1) & 1];
    float*       hout = g_h[t & 1];

    const int tid = threadIdx.x;
    const int m0 = blockIdx.x * 64, n0 = blockIdx.y * 64;
    const int ty = tid >> 4, tx = tid & 15;  // compute tile: m = ty*4+i, n = tx*4+j
    const int sm = tid >> 2, skq = tid & 3;  // staging: row = tid/4, k-quad = tid%4

    unsigned long long acc[3][4][2];
    #pragma unroll
    for (int g = 0; g < 3; g++)
        #pragma unroll
        for (int i = 0; i < 4; i++) { acc[g][i][0] = 0ull; acc[g][i][1] = 0ull; }

    for (int kk = 0; kk < DD; kk += 16) {
        // global loads first (overlap with previous tile's compute)
        float4 av  = *(const float4*)&hin[(size_t)(m0 + sm) * DD + kk + skq * 4];
        float4 bv0 = *(const float4*)&Whh[(size_t)(0 * DD + n0 + sm) * DD + kk + skq * 4];
        float4 bv1 = *(const float4*)&Whh[(size_t)(1 * DD + n0 + sm) * DD + kk + skq * 4];
        float4 bv2 = *(const float4*)&Whh[(size_t)(2 * DD + n0 + sm) * DD + kk + skq * 4];
        __syncthreads();  // previous iteration's reads done
        As[skq * 4 + 0][sm] = make_float2(av.x, av.x);
        As[skq * 4 + 1][sm] = make_float2(av.y, av.y);
        As[skq * 4 + 2][sm] = make_float2(av.z, av.z);
        As[skq * 4 + 3][sm] = make_float2(av.w, av.w);
        Bs[0][skq * 4 + 0][sm] = bv0.x; Bs[0][skq * 4 + 1][sm] = bv0.y;
        Bs[0][skq * 4 + 2][sm] = bv0.z; Bs[0][skq * 4 + 3][sm] = bv0.w;
        Bs[1][skq * 4 + 0][sm] = bv1.x; Bs[1][skq * 4 + 1][sm] = bv1.y;
        Bs[1][skq * 4 + 2][sm] = bv1.z; Bs[1][skq * 4 + 3][sm] = bv1.w;
        Bs[2][skq * 4 + 0][sm] = bv2.x; Bs[2][skq * 4 + 1][sm] = bv2.y;
        Bs[2][skq * 4 + 2][sm] = bv2.z; Bs[2][skq * 4 + 3][sm] = bv2.w;
        __syncthreads();

        #pragma unroll
        for (int k = 0; k < 16; k++) {
            ulonglong2 a01 = *(const ulonglong2*)&As[k][ty * 4];
            ulonglong2 a23 = *(const ulonglong2*)&As[k][ty * 4 + 2];
            ulonglong2 br  = *(const ulonglong2*)&Bs[0][k][tx * 4];
            ulonglong2 bz  = *(const ulonglong2*)&Bs[1][k][tx * 4];
            ulonglong2 bn  = *(const ulonglong2*)&Bs[2][k][tx * 4];
            unsigned long long a[4] = {a01.x, a01.y, a23.x, a23.y};
            #pragma unroll
            for (int i = 0; i < 4; i++) {
                FMA2(acc[0][i][0], a[i], br.x); FMA2(acc[0][i][1], a[i], br.y);
                FMA2(acc[1][i][0], a[i], bz.x); FMA2(acc[1][i][1], a[i], bz.y);
                FMA2(acc[2][i][0], a[i], bn.x); FMA2(acc[2][i][1], a[i], bn.y);
            }
        }
    }

    // Epilogue: gates. gi from table (b_ih + b_hh r/z folded in), b_hh_n added here.
    const float4 bhn4 = *(const float4*)&bhh[2 * DD + n0 + tx * 4];
    #pragma unroll
    for (int i = 0; i < 4; i++) {
        int m = m0 + ty * 4 + i;
        int tok = g_tok[m];
        const float* tab = g_tab + (size_t)tok * G3 + n0 + tx * 4;
        float4 gir  = *(const float4*)(tab);
        float4 giz  = *(const float4*)(tab + DD);
        float4 gin  = *(const float4*)(tab + 2 * DD);
        float4 hold = *(const float4*)&hin[(size_t)m * DD + n0 + tx * 4];

        float gr[4], gz[4], gn[4];
        gr[0] = lo32(acc[0][i][0]); gr[1] = hi32(acc[0][i][0]);
        gr[2] = lo32(acc[0][i][1]); gr[3] = hi32(acc[0][i][1]);
        gz[0] = lo32(acc[1][i][0]); gz[1] = hi32(acc[1][i][0]);
        gz[2] = lo32(acc[1][i][1]); gz[3] = hi32(acc[1][i][1]);
        gn[0] = lo32(acc[2][i][0]); gn[1] = hi32(acc[2][i][0]);
        gn[2] = lo32(acc[2][i][1]); gn[3] = hi32(acc[2][i][1]);

        float ir[4] = {gir.x, gir.y, gir.z, gir.w};
        float iz[4] = {giz.x, giz.y, giz.z, giz.w};
        float in_[4] = {gin.x, gin.y, gin.z, gin.w};
        float bn_[4] = {bhn4.x, bhn4.y, bhn4.z, bhn4.w};
        float ho[4] = {hold.x, hold.y, hold.z, hold.w};
        float o[4];
        #pragma unroll
        for (int j = 0; j < 4; j++) {
            float r = sigm(ir[j] + gr[j]);
            float z = sigm(iz[j] + gz[j]);
            float n = tanhf(in_[j] + r * (gn[j] + bn_[j]));
            o[j] = (1.f - z) * n + z * ho[j];
        }
        *(float4*)&hout[(size_t)m * DD + n0 + tx * 4] =
            make_float4(o[0], o[1], o[2], o[3]);
    }
}

// ---------------------------------------------------------------------------
// Kernel 2: logits = h_new @ W_proj^T + b_proj; write logits [B,C,T];
// per-row argmax (first-max semantics) -> g_tok and tokens [B,T].
// grid BB/16 = 128 blocks, 256 threads. Tile: 16 rows x all 128 classes.
// ---------------------------------------------------------------------------
__global__ __launch_bounds__(256)
void step_out(const float* __restrict__ Wp, const float* __restrict__ bp,
              float* __restrict__ out, int t) {
    __shared__ float As[32][17];                  // [k][m]
    __shared__ __align__(16) float Bs[32][132];   // [k][c]
    const float* h = g_h[t & 1];
    const int tid = threadIdx.x;
    const int tx = tid & 31, ty = tid >> 5;       // warp = one ty; lane = tx
    const int m0 = blockIdx.x * 16;

    float acc[2][4] = {{0.f, 0.f, 0.f, 0.f}, {0.f, 0.f, 0.f, 0.f}};

    for (int kk = 0; kk < DD; kk += 32) {
        int k = tid & 31, m = tid >> 5;  // m in 0..7
        float a0v = h[(size_t)(m0 + m) * DD + kk + k];
        float a1v = h[(size_t)(m0 + m + 8) * DD + kk + k];
        float4 w[4];
        #pragma unroll
        for (int r = 0; r < 4; r++) {
            int c = (tid >> 3) + r * 32, kq = tid & 7;
            w[r] = *(const float4*)&Wp[(size_t)c * DD + kk + kq * 4];
        }
        __syncthreads();
        As[k][m] = a0v;
        As[k][m + 8] = a1v;
        #pragma unroll
        for (int r = 0; r < 4; r++) {
            int c = (tid >> 3) + r * 32, kq = tid & 7;
            Bs[kq * 4 + 0][c] = w[r].x; Bs[kq * 4 + 1][c] = w[r].y;
            Bs[kq * 4 + 2][c] = w[r].z; Bs[kq * 4 + 3][c] = w[r].w;
        }
        __syncthreads();
        #pragma unroll
        for (int k2 = 0; k2 < 32; k2++) {
            float a0 = As[k2][2 * ty], a1 = As[k2][2 * ty + 1];
            float4 b = *(const float4*)&Bs[k2][tx * 4];
            acc[0][0] += a0 * b.x; acc[0][1] += a0 * b.y;
            acc[0][2] += a0 * b.z; acc[0][3] += a0 * b.w;
            acc[1][0] += a1 * b.x; acc[1][1] += a1 * b.y;
            acc[1][2] += a1 * b.z; acc[1][3] += a1 * b.w;
        }
    }

    float* out_tok = out + (size_t)BB * CC * TT;
    #pragma unroll
    for (int i = 0; i < 2; i++) {
        int b = m0 + 2 * ty + i;
        float bv = -3.402823466e38f;
        int bi = 0;
        #pragma unroll
        for (int j = 0; j < 4; j++) {
            int c = tx * 4 + j;
            float v = acc[i][j] + bp[c];
            out[(size_t)b * (CC * TT) + (size_t)c * TT + t] = v;
            if (v > bv) { bv = v; bi = c; }   // strict > keeps first max
        }
        #pragma unroll
        for (int off = 16; off; off >>= 1) {
            float ov = __shfl_xor_sync(0xffffffffu, bv, off);
            int   oi = __shfl_xor_sync(0xffffffffu, bi, off);
            if (ov > bv || (ov == bv && oi < bi)) { bv = ov; bi = oi; }
        }
        if (tx == 0) {
            g_tok[b] = bi;
            out_tok[(size_t)b * TT + t] = (float)bi;
        }
    }
}

// ---------------------------------------------------------------------------
// kernel_launch: graph-capturable, 304 kernel nodes, no allocation.
// Inputs (metadata order): feat, W_ih, W_hh, b_ih, b_hh, W_proj, b_proj, embed
// Output: logits [B,C,T] float32 then tokens [B,T] as float32.
// ---------------------------------------------------------------------------
extern "C" void kernel_launch(void* const* d_in, const int* in_sizes, int n_in,
                              void* d_out, int out_size) {
    const float* feat  = (const float*)d_in[0];
    const float* Wih   = (const float*)d_in[1];
    const float* Whh   = (const float*)d_in[2];
    const float* bih   = (const float*)d_in[3];
    const float* bhh   = (const float*)d_in[4];
    const float* Wp    = (const float*)d_in[5];
    const float* bp    = (const float*)d_in[6];
    const float* embed = (const float*)d_in[7];
    float* out = (float*)d_out;

    build_tab<<<dim3(CC + 1, G3 / 256), 256>>>(Wih, bih, bhh, embed);
    init_tok<<<(BB + 255) / 256, 256>>>();

    for (int t = 0; t < TT; t++) {
        step_h<<<dim3(BB / 64, DD / 64), 256>>>(feat, Whh, bhh, t);
        step_out<<<BB / 16, 256>>>(Wp, bp, out, t);
    }
}

// round 7
// speedup vs baseline: 1.0000x; 1.0000x over previous
#include <cuda_runtime.h>
#include <math.h>

// Problem constants
#define BB 2048   // batch
#define DD 512    // hidden
#define CC 128    // vocab
#define TT 151    // steps
#define G3 1536   // 3*DD

// Persistent scratch (allowed: __device__ globals, no runtime allocation)
__device__ float g_h[2][BB * DD];            // ping-pong hidden state, 8 MB
__device__ float g_tab[(CC + 1) * G3];       // gi table: embed@W_ih^T + b_ih (+ b_hh r/z folded)
__device__ int   g_tok[BB];                  // previous token per batch row
__device__ float g_log[(size_t)BB * TT * CC]; // logits staged [B,T,C] (coalesced), 158 MB

__device__ __forceinline__ float sigm(float x) { return 1.f / (1.f + expf(-x)); }

// Packed fp32x2 FMA (Blackwell FFMA2; only reachable via PTX fma.rn.f32x2)
#define FMA2(acc, a, b) \
    asm("fma.rn.f32x2 %0, %1, %2, %0;" : "+l"(acc) : "l"(a), "l"(b))

__device__ __forceinline__ float lo32(unsigned long long v) { return __uint_as_float((unsigned)v); }
__device__ __forceinline__ float hi32(unsigned long long v) { return __uint_as_float((unsigned)(v >> 32)); }

// ---------------------------------------------------------------------------
// Precompute gi table: g_tab[c][j] = embed[c]·W_ih[j] + b_ih[j] + (j<1024 ? b_hh[j] : 0)
// Row CC (=128) is the zero-input row (t=0): just the biases.
// ---------------------------------------------------------------------------
__global__ void build_tab(const float* __restrict__ Wih, const float* __restrict__ bih,
                          const float* __restrict__ bhh, const float* __restrict__ embed) {
    __shared__ float se[DD];
    int c = blockIdx.x;                      // 0..128
    int j = blockIdx.y * 256 + threadIdx.x;  // 0..1535
    for (int i = threadIdx.x; i < DD; i += 256)
        se[i] = (c < CC) ? embed[c * DD + i] : 0.f;
    __syncthreads();
    float acc = bih[j] + (j < 2 * DD ? bhh[j] : 0.f);
    if (c < CC) {
        const float4* w  = (const float4*)(Wih + (size_t)j * DD);
        const float4* s4 = (const float4*)se;
        #pragma unroll 8
        for (int k = 0; k < DD / 4; k++) {
            float4 wv = w[k], sv = s4[k];
            acc += wv.x * sv.x;
            acc += wv.y * sv.y;
            acc += wv.z * sv.z;
            acc += wv.w * sv.w;
        }
    }
    g_tab[(size_t)c * G3 + j] = acc;
}

__global__ void init_tok() {
    int i = blockIdx.x * blockDim.x + threadIdx.x;
    if (i < BB) g_tok[i] = CC;  // zero-input table row
}

// ---------------------------------------------------------------------------
// Kernel 1: gh = h @ W_hh^T, fused gates + gi table lookup -> h_new
// grid (BB/64, DD/64) = (32, 8), 256 threads, occ 2.
// Double-buffered K=16 panels: one barrier per panel, LDG latency hidden
// under a full panel of FFMA2 compute. Arithmetic identical to prior round.
// ---------------------------------------------------------------------------
__device__ __forceinline__ void store_panel(float2 (*As)[66], float (*Bs)[16][68],
                                            int sm, int skq,
                                            float4 av, float4 bv0, float4 bv1, float4 bv2) {
    As[skq * 4 + 0][sm] = make_float2(av.x, av.x);
    As[skq * 4 + 1][sm] = make_float2(av.y, av.y);
    As[skq * 4 + 2][sm] = make_float2(av.z, av.z);
    As[skq * 4 + 3][sm] = make_float2(av.w, av.w);
    Bs[0][skq * 4 + 0][sm] = bv0.x; Bs[0][skq * 4 + 1][sm] = bv0.y;
    Bs[0][skq * 4 + 2][sm] = bv0.z; Bs[0][skq * 4 + 3][sm] = bv0.w;
    Bs[1][skq * 4 + 0][sm] = bv1.x; Bs[1][skq * 4 + 1][sm] = bv1.y;
    Bs[1][skq * 4 + 2][sm] = bv1.z; Bs[1][skq * 4 + 3][sm] = bv1.w;
    Bs[2][skq * 4 + 0][sm] = bv2.x; Bs[2][skq * 4 + 1][sm] = bv2.y;
    Bs[2][skq * 4 + 2][sm] = bv2.z; Bs[2][skq * 4 + 3][sm] = bv2.w;
}

__global__ __launch_bounds__(256, 2)
void step_h(const float* __restrict__ feat, const float* __restrict__ Whh,
            const float* __restrict__ bhh, int t) {
    __shared__ __align__(16) float2 As[2][16][66];     // [buf][k][m], duplicated lanes
    __shared__ __align__(16) float  Bs[2][3][16][68];  // [buf][gate][k][n]

    const float* hin  = (t == 0) ? feat : g_h[(t - 1) & 1];
    float*       hout = g_h[t & 1];

    const int tid = threadIdx.x;
    const int m0 = blockIdx.x * 64, n0 = blockIdx.y * 64;
    const int ty = tid >> 4, tx = tid & 15;  // compute tile: m = ty*4+i, n = tx*4+j
    const int sm = tid >> 2, skq = tid & 3;  // staging: row = tid/4, k-quad = tid%4

    const float* pa  = hin + (size_t)(m0 + sm) * DD + skq * 4;
    const float* pb0 = Whh + (size_t)(n0 + sm) * DD + skq * 4;
    const float* pb1 = pb0 + (size_t)DD * DD;
    const float* pb2 = pb1 + (size_t)DD * DD;

    unsigned long long acc[3][4][2];
    #pragma unroll
    for (int g = 0; g < 3; g++)
        #pragma unroll
        for (int i = 0; i < 4; i++) { acc[g][i][0] = 0ull; acc[g][i][1] = 0ull; }

    // Prologue: panel 0 -> buf 0; load panel 1 into regs.
    float4 av, bv0, bv1, bv2;
    av  = *(const float4*)(pa);
    bv0 = *(const float4*)(pb0);
    bv1 = *(const float4*)(pb1);
    bv2 = *(const float4*)(pb2);
    store_panel(As[0], Bs[0], sm, skq, av, bv0, bv1, bv2);
    av  = *(const float4*)(pa  + 16);
    bv0 = *(const float4*)(pb0 + 16);
    bv1 = *(const float4*)(pb1 + 16);
    bv2 = *(const float4*)(pb2 + 16);
    __syncthreads();

    for (int p = 0; p < 32; p++) {
        const int s = p & 1;
        if (p < 31)
            store_panel(As[s ^ 1], Bs[s ^ 1], sm, skq, av, bv0, bv1, bv2);
        if (p < 30) {
            const int kk = (p + 2) * 16;
            av  = *(const float4*)(pa  + kk);
            bv0 = *(const float4*)(pb0 + kk);
            bv1 = *(const float4*)(pb1 + kk);
            bv2 = *(const float4*)(pb2 + kk);
        }
        #pragma unroll
        for (int k = 0; k < 16; k++) {
            ulonglong2 a01 = *(const ulonglong2*)&As[s][k][ty * 4];
            ulonglong2 a23 = *(const ulonglong2*)&As[s][k][ty * 4 + 2];
            ulonglong2 br  = *(const ulonglong2*)&Bs[s][0][k][tx * 4];
            ulonglong2 bz  = *(const ulonglong2*)&Bs[s][1][k][tx * 4];
            ulonglong2 bn  = *(const ulonglong2*)&Bs[s][2][k][tx * 4];
            unsigned long long a[4] = {a01.x, a01.y, a23.x, a23.y};
            #pragma unroll
            for (int i = 0; i < 4; i++) {
                FMA2(acc[0][i][0], a[i], br.x); FMA2(acc[0][i][1], a[i], br.y);
                FMA2(acc[1][i][0], a[i], bz.x); FMA2(acc[1][i][1], a[i], bz.y);
                FMA2(acc[2][i][0], a[i], bn.x); FMA2(acc[2][i][1], a[i], bn.y);
            }
        }
        __syncthreads();
    }

    // Epilogue: gates. gi from table (b_ih + b_hh r/z folded in), b_hh_n added here.
    const float4 bhn4 = *(const float4*)&bhh[2 * DD + n0 + tx * 4];
    #pragma unroll
    for (int i = 0; i < 4; i++) {
        int m = m0 + ty * 4 + i;
        int tok = g_tok[m];
        const float* tab = g_tab + (size_t)tok * G3 + n0 + tx * 4;
        float4 gir  = *(const float4*)(tab);
        float4 giz  = *(const float4*)(tab + DD);
        float4 gin  = *(const float4*)(tab + 2 * DD);
        float4 hold = *(const float4*)&hin[(size_t)m * DD + n0 + tx * 4];

        float gr[4], gz[4], gn[4];
        gr[0] = lo32(acc[0][i][0]); gr[1] = hi32(acc[0][i][0]);
        gr[2] = lo32(acc[0][i][1]); gr[3] = hi32(acc[0][i][1]);
        gz[0] = lo32(acc[1][i][0]); gz[1] = hi32(acc[1][i][0]);
        gz[2] = lo32(acc[1][i][1]); gz[3] = hi32(acc[1][i][1]);
        gn[0] = lo32(acc[2][i][0]); gn[1] = hi32(acc[2][i][0]);
        gn[2] = lo32(acc[2][i][1]); gn[3] = hi32(acc[2][i][1]);

        float ir[4] = {gir.x, gir.y, gir.z, gir.w};
        float iz[4] = {giz.x, giz.y, giz.z, giz.w};
        float in_[4] = {gin.x, gin.y, gin.z, gin.w};
        float bn_[4] = {bhn4.x, bhn4.y, bhn4.z, bhn4.w};
        float ho[4] = {hold.x, hold.y, hold.z, hold.w};
        float o[4];
        #pragma unroll
        for (int j = 0; j < 4; j++) {
            float r = sigm(ir[j] + gr[j]);
            float z = sigm(iz[j] + gz[j]);
            float n = tanhf(in_[j] + r * (gn[j] + bn_[j]));
            o[j] = (1.f - z) * n + z * ho[j];
        }
        *(float4*)&hout[(size_t)m * DD + n0 + tx * 4] =
            make_float4(o[0], o[1], o[2], o[3]);
    }
}

// ---------------------------------------------------------------------------
// Kernel 2: logits = h_new @ W_proj^T + b_proj; stage logits [B,T,C] coalesced;
// per-row argmax (first-max semantics) -> g_tok and tokens [B,T].
// grid BB/8 = 256 blocks, 256 threads. One warp per batch row, 4 classes/lane.
// Summation order over k identical to prior round -> bitwise-same logits.
// ---------------------------------------------------------------------------
__global__ __launch_bounds__(256)
void step_out(const float* __restrict__ Wp, const float* __restrict__ bp,
              float* __restrict__ out, int t) {
    __shared__ float As[32][9];                   // [k][m], broadcast reads
    __shared__ __align__(16) float Bs[32][132];   // [k][c]
    const float* h = g_h[t & 1];
    const int tid = threadIdx.x;
    const int tx = tid & 31, ty = tid >> 5;       // warp ty owns row m0+ty; lane tx
    const int m0 = blockIdx.x * 8;

    float acc[4] = {0.f, 0.f, 0.f, 0.f};

    for (int kk = 0; kk < DD; kk += 32) {
        int k = tid & 31, m = tid >> 5;           // m in 0..7
        float a0v = h[(size_t)(m0 + m) * DD + kk + k];
        float4 w[4];
        #pragma unroll
        for (int r = 0; r < 4; r++) {
            int c = (tid >> 3) + r * 32, kq = tid & 7;
            w[r] = *(const float4*)&Wp[(size_t)c * DD + kk + kq * 4];
        }
        __syncthreads();
        As[k][m] = a0v;
        #pragma unroll
        for (int r = 0; r < 4; r++) {
            int c = (tid >> 3) + r * 32, kq = tid & 7;
            Bs[kq * 4 + 0][c] = w[r].x; Bs[kq * 4 + 1][c] = w[r].y;
            Bs[kq * 4 + 2][c] = w[r].z; Bs[kq * 4 + 3][c] = w[r].w;
        }
        __syncthreads();
        #pragma unroll
        for (int k2 = 0; k2 < 32; k2++) {
            float a = As[k2][ty];
            float4 b = *(const float4*)&Bs[k2][tx * 4];
            acc[0] += a * b.x; acc[1] += a * b.y;
            acc[2] += a * b.z; acc[3] += a * b.w;
        }
    }

    float* out_tok = out + (size_t)BB * CC * TT;
    const float4 bpv = *(const float4*)&bp[tx * 4];
    int b = m0 + ty;

    float v0 = acc[0] + bpv.x, v1 = acc[1] + bpv.y;
    float v2 = acc[2] + bpv.z, v3 = acc[3] + bpv.w;
    *(float4*)&g_log[((size_t)b * TT + t) * CC + tx * 4] =
        make_float4(v0, v1, v2, v3);

    // argmax, first-max semantics
    float bv = -3.402823466e38f;
    int bi = 0;
    float vv[4] = {v0, v1, v2, v3};
    #pragma unroll
    for (int j = 0; j < 4; j++) {
        if (vv[j] > bv) { bv = vv[j]; bi = tx * 4 + j; }
    }
    #pragma unroll
    for (int off = 16; off; off >>= 1) {
        float ov = __shfl_xor_sync(0xffffffffu, bv, off);
        int   oi = __shfl_xor_sync(0xffffffffu, bi, off);
        if (ov > bv || (ov == bv && oi < bi)) { bv = ov; bi = oi; }
    }
    if (tx == 0) {
        g_tok[b] = bi;
        out_tok[(size_t)b * TT + t] = (float)bi;
    }
}

// ---------------------------------------------------------------------------
// Kernel 3 (once, at end): transpose staged logits [B,T,C] -> d_out [B,C,T].
// 32x32 smem tiles; both global read and write fully coalesced.
// ---------------------------------------------------------------------------
__global__ __launch_bounds__(256)
void transp(float* __restrict__ out) {
    __shared__ float tile[32][33];
    const int b  = blockIdx.z;
    const int t0 = blockIdx.x * 32, c0 = blockIdx.y * 32;
    const int tx = threadIdx.x, ty = threadIdx.y;

    #pragma unroll
    for (int i = ty; i < 32; i += 8) {
        int t = t0 + i;
        if (t < TT)
            tile[i][tx] = g_log[((size_t)b * TT + t) * CC + c0 + tx];
    }
    __syncthreads();
    #pragma unroll
    for (int i = ty; i < 32; i += 8) {
        int c = c0 + i;
        int t = t0 + tx;
        if (t < TT)
            out[((size_t)b * CC + c) * TT + t] = tile[tx][i];
    }
}

// ---------------------------------------------------------------------------
// kernel_launch: graph-capturable, no allocation.
// Inputs (metadata order): feat, W_ih, W_hh, b_ih, b_hh, W_proj, b_proj, embed
// Output: logits [B,C,T] float32 then tokens [B,T] as float32.
// ---------------------------------------------------------------------------
extern "C" void kernel_launch(void* const* d_in, const int* in_sizes, int n_in,
                              void* d_out, int out_size) {
    const float* feat  = (const float*)d_in[0];
    const float* Wih   = (const float*)d_in[1];
    const float* Whh   = (const float*)d_in[2];
    const float* bih   = (const float*)d_in[3];
    const float* bhh   = (const float*)d_in[4];
    const float* Wp    = (const float*)d_in[5];
    const float* bp    = (const float*)d_in[6];
    const float* embed = (const float*)d_in[7];
    float* out = (float*)d_out;

    build_tab<<<dim3(CC + 1, G3 / 256), 256>>>(Wih, bih, bhh, embed);
    init_tok<<<(BB + 255) / 256, 256>>>();

    for (int t = 0; t < TT; t++) {
        step_h<<<dim3(BB / 64, DD / 64), 256>>>(feat, Whh, bhh, t);
        step_out<<<BB / 8, 256>>>(Wp, bp, out, t);
    }

    transp<<<dim3((TT + 31) / 32, CC / 32, BB), dim3(32, 8)>>>(out);
}

// round 10
// speedup vs baseline: 1.2155x; 1.2155x over previous
#include <cuda_runtime.h>
#include <math.h>

// Problem constants
#define BB 2048   // batch
#define DD 512    // hidden
#define CC 128    // vocab
#define TT 151    // steps
#define G3 1536   // 3*DD

// Persistent scratch (allowed: __device__ globals, no runtime allocation)
__device__ float g_h[2][BB * DD];             // ping-pong hidden state, 8 MB
__device__ float g_tab[(CC + 1) * G3];        // gi table: embed@W_ih^T + b_ih (+ b_hh r/z folded)
__device__ int   g_tok[BB];                   // previous token per batch row
__device__ float g_log[(size_t)BB * TT * CC]; // logits staged [B,T,C] (coalesced), 158 MB
__device__ float g_part[8 * BB * CC];         // projection partials [n_tile][B][C], 8 MB
__device__ float g_wpt[DD * CC];              // W_proj transposed [D][C], 256 KB

__device__ __forceinline__ float sigm(float x) { return 1.f / (1.f + expf(-x)); }

// Packed fp32x2 FMA (Blackwell FFMA2; only reachable via PTX fma.rn.f32x2)
#define FMA2(acc, a, b) \
    asm("fma.rn.f32x2 %0, %1, %2, %0;" : "+l"(acc) : "l"(a), "l"(b))

__device__ __forceinline__ float lo32(unsigned long long v) { return __uint_as_float((unsigned)v); }
__device__ __forceinline__ float hi32(unsigned long long v) { return __uint_as_float((unsigned)(v >> 32)); }

// ---------------------------------------------------------------------------
// Precompute gi table: g_tab[c][j] = embed[c]·W_ih[j] + b_ih[j] + (j<1024 ? b_hh[j] : 0)
// Row CC (=128) is the zero-input row (t=0): just the biases.
// ---------------------------------------------------------------------------
__global__ void build_tab(const float* __restrict__ Wih, const float* __restrict__ bih,
                          const float* __restrict__ bhh, const float* __restrict__ embed) {
    __shared__ float se[DD];
    int c = blockIdx.x;                      // 0..128
    int j = blockIdx.y * 256 + threadIdx.x;  // 0..1535
    for (int i = threadIdx.x; i < DD; i += 256)
        se[i] = (c < CC) ? embed[c * DD + i] : 0.f;
    __syncthreads();
    float acc = bih[j] + (j < 2 * DD ? bhh[j] : 0.f);
    if (c < CC) {
        const float4* w  = (const float4*)(Wih + (size_t)j * DD);
        const float4* s4 = (const float4*)se;
        #pragma unroll 8
        for (int k = 0; k < DD / 4; k++) {
            float4 wv = w[k], sv = s4[k];
            acc += wv.x * sv.x;
            acc += wv.y * sv.y;
            acc += wv.z * sv.z;
            acc += wv.w * sv.w;
        }
    }
    g_tab[(size_t)c * G3 + j] = acc;
}

// W_proj^T: g_wpt[n][c] = Wp[c][n]  (one-time, coalesced writes)
__global__ void build_wpt(const float* __restrict__ Wp) {
    int i = blockIdx.x * 256 + threadIdx.x;  // 0 .. 512*128-1
    int n = i >> 7, c = i & 127;
    g_wpt[n * CC + c] = Wp[(size_t)c * DD + n];
}

__global__ void init_tok() {
    int i = blockIdx.x * blockDim.x + threadIdx.x;
    if (i < BB) g_tok[i] = CC;  // zero-input table row
}

// ---------------------------------------------------------------------------
// Kernel 1: gh = h @ W_hh^T, fused gates + gi table lookup -> h_new,
//           PLUS this CTA's 64-col partial of the projection h_new @ Wp^T.
// grid (BB/64, DD/64) = (32, 8), 256 threads, occ 2.
// ---------------------------------------------------------------------------
__device__ __forceinline__ void store_panel(float2 (*As)[66], float (*Bs)[16][68],
                                            int sm, int skq,
                                            float4 av, float4 bv0, float4 bv1, float4 bv2) {
    As[skq * 4 + 0][sm] = make_float2(av.x, av.x);
    As[skq * 4 + 1][sm] = make_float2(av.y, av.y);
    As[skq * 4 + 2][sm] = make_float2(av.z, av.z);
    As[skq * 4 + 3][sm] = make_float2(av.w, av.w);
    Bs[0][skq * 4 + 0][sm] = bv0.x; Bs[0][skq * 4 + 1][sm] = bv0.y;
    Bs[0][skq * 4 + 2][sm] = bv0.z; Bs[0][skq * 4 + 3][sm] = bv0.w;
    Bs[1][skq * 4 + 0][sm] = bv1.x; Bs[1][skq * 4 + 1][sm] = bv1.y;
    Bs[1][skq * 4 + 2][sm] = bv1.z; Bs[1][skq * 4 + 3][sm] = bv1.w;
    Bs[2][skq * 4 + 0][sm] = bv2.x; Bs[2][skq * 4 + 1][sm] = bv2.y;
    Bs[2][skq * 4 + 2][sm] = bv2.z; Bs[2][skq * 4 + 3][sm] = bv2.w;
}

__global__ __launch_bounds__(256, 2)
void step_h(const float* __restrict__ feat, const float* __restrict__ Whh,
            const float* __restrict__ bhh, int t) {
    // Raw smem carved into phase-disjoint views:
    //   GEMM phase:  As[2][16][66] float2 (16896 B) + Bs[2][3][16][68] float (26112 B)
    //   Proj phase:  Hs[64][68] float (17408 B), overlapping As + head of Bs
    __shared__ __align__(16) unsigned char sraw[43008];
    typedef float2 A_t[16][66];
    A_t* Asb = (A_t*)sraw;
    float (*Bsb)[3][16][68] = (float(*)[3][16][68])(sraw + 16896);
    float* Hs = (float*)sraw;  // stride 68

    const float* hin  = (t == 0) ? feat : g_h[(t - 1) & 1];
    float*       hout = g_h[t & 1];

    const int tid = threadIdx.x;
    const int m0 = blockIdx.x * 64, n0 = blockIdx.y * 64;
    const int ty = tid >> 4, tx = tid & 15;  // compute tile: m = ty*4+i, n = tx*4+j
    const int sm = tid >> 2, skq = tid & 3;  // staging: row = tid/4, k-quad = tid%4

    const float* pa  = hin + (size_t)(m0 + sm) * DD + skq * 4;
    const float* pb0 = Whh + (size_t)(n0 + sm) * DD + skq * 4;
    const float* pb1 = pb0 + (size_t)DD * DD;
    const float* pb2 = pb1 + (size_t)DD * DD;

    unsigned long long acc[3][4][2];
    #pragma unroll
    for (int g = 0; g < 3; g++)
        #pragma unroll
        for (int i = 0; i < 4; i++) { acc[g][i][0] = 0ull; acc[g][i][1] = 0ull; }

    // Prologue: panel 0 -> buf 0; load panel 1 into regs.
    float4 av, bv0, bv1, bv2;
    av  = *(const float4*)(pa);
    bv0 = *(const float4*)(pb0);
    bv1 = *(const float4*)(pb1);
    bv2 = *(const float4*)(pb2);
    store_panel(Asb[0], Bsb[0], sm, skq, av, bv0, bv1, bv2);
    av  = *(const float4*)(pa  + 16);
    bv0 = *(const float4*)(pb0 + 16);
    bv1 = *(const float4*)(pb1 + 16);
    bv2 = *(const float4*)(pb2 + 16);
    __syncthreads();

    for (int p = 0; p < 32; p++) {
        const int s = p & 1;
        if (p < 31)
            store_panel(Asb[s ^ 1], Bsb[s ^ 1], sm, skq, av, bv0, bv1, bv2);
        if (p < 30) {
            const int kk = (p + 2) * 16;
            av  = *(const float4*)(pa  + kk);
            bv0 = *(const float4*)(pb0 + kk);
            bv1 = *(const float4*)(pb1 + kk);
            bv2 = *(const float4*)(pb2 + kk);
        }
        #pragma unroll
        for (int k = 0; k < 16; k++) {
            ulonglong2 a01 = *(const ulonglong2*)&Asb[s][k][ty * 4];
            ulonglong2 a23 = *(const ulonglong2*)&Asb[s][k][ty * 4 + 2];
            ulonglong2 br  = *(const ulonglong2*)&Bsb[s][0][k][tx * 4];
            ulonglong2 bz  = *(const ulonglong2*)&Bsb[s][1][k][tx * 4];
            ulonglong2 bn  = *(const ulonglong2*)&Bsb[s][2][k][tx * 4];
            unsigned long long a[4] = {a01.x, a01.y, a23.x, a23.y};
            #pragma unroll
            for (int i = 0; i < 4; i++) {
                FMA2(acc[0][i][0], a[i], br.x); FMA2(acc[0][i][1], a[i], br.y);
                FMA2(acc[1][i][0], a[i], bz.x); FMA2(acc[1][i][1], a[i], bz.y);
                FMA2(acc[2][i][0], a[i], bn.x); FMA2(acc[2][i][1], a[i], bn.y);
            }
        }
        __syncthreads();
    }

    // Gate epilogue: gi from table (b_ih + b_hh r/z folded in), b_hh_n added here.
    // Write h_new to global AND to Hs (smem) for the fused projection partial.
    const float4 bhn4 = *(const float4*)&bhh[2 * DD + n0 + tx * 4];
    #pragma unroll
    for (int i = 0; i < 4; i++) {
        int m = m0 + ty * 4 + i;
        int tok = g_tok[m];
        const float* tab = g_tab + (size_t)tok * G3 + n0 + tx * 4;
        float4 gir  = *(const float4*)(tab);
        float4 giz  = *(const float4*)(tab + DD);
        float4 gin  = *(const float4*)(tab + 2 * DD);
        float4 hold = *(const float4*)&hin[(size_t)m * DD + n0 + tx * 4];

        float gr[4], gz[4], gn[4];
        gr[0] = lo32(acc[0][i][0]); gr[1] = hi32(acc[0][i][0]);
        gr[2] = lo32(acc[0][i][1]); gr[3] = hi32(acc[0][i][1]);
        gz[0] = lo32(acc[1][i][0]); gz[1] = hi32(acc[1][i][0]);
        gz[2] = lo32(acc[1][i][1]); gz[3] = hi32(acc[1][i][1]);
        gn[0] = lo32(acc[2][i][0]); gn[1] = hi32(acc[2][i][0]);
        gn[2] = lo32(acc[2][i][1]); gn[3] = hi32(acc[2][i][1]);

        float ir[4] = {gir.x, gir.y, gir.z, gir.w};
        float iz[4] = {giz.x, giz.y, giz.z, giz.w};
        float in_[4] = {gin.x, gin.y, gin.z, gin.w};
        float bn_[4] = {bhn4.x, bhn4.y, bhn4.z, bhn4.w};
        float ho[4] = {hold.x, hold.y, hold.z, hold.w};
        float o[4];
        #pragma unroll
        for (int j = 0; j < 4; j++) {
            float r = sigm(ir[j] + gr[j]);
            float z = sigm(iz[j] + gz[j]);
            float n = tanhf(in_[j] + r * (gn[j] + bn_[j]));
            o[j] = (1.f - z) * n + z * ho[j];
            Hs[(ty * 4 + i) * 68 + tx * 4 + j] = o[j];
        }
        *(float4*)&hout[(size_t)m * DD + n0 + tx * 4] =
            make_float4(o[0], o[1], o[2], o[3]);
    }
    __syncthreads();

    // Projection partial: P[m][c] = sum_{k=0..63} Hs[m][k] * WpT[n0+k][c]
    // Warp w owns rows w*8..w*8+7; lane owns 4 classes (c = lane*4..+3).
    {
        const int w = tid >> 5, lane = tid & 31;
        float4 pacc[8];
        #pragma unroll
        for (int rr = 0; rr < 8; rr++) pacc[rr] = make_float4(0.f, 0.f, 0.f, 0.f);

        #pragma unroll 4
        for (int kq = 0; kq < 16; kq++) {
            const float* wr = g_wpt + (size_t)(n0 + kq * 4) * CC + lane * 4;
            float4 w0 = *(const float4*)(wr);
            float4 w1 = *(const float4*)(wr + CC);
            float4 w2 = *(const float4*)(wr + 2 * CC);
            float4 w3 = *(const float4*)(wr + 3 * CC);
            #pragma unroll
            for (int rr = 0; rr < 8; rr++) {
                float4 a4 = *(const float4*)&Hs[(w * 8 + rr) * 68 + kq * 4];
                pacc[rr].x += a4.x * w0.x; pacc[rr].y += a4.x * w0.y;
                pacc[rr].z += a4.x * w0.z; pacc[rr].w += a4.x * w0.w;
                pacc[rr].x += a4.y * w1.x; pacc[rr].y += a4.y * w1.y;
                pacc[rr].z += a4.y * w1.z; pacc[rr].w += a4.y * w1.w;
                pacc[rr].x += a4.z * w2.x; pacc[rr].y += a4.z * w2.y;
                pacc[rr].z += a4.z * w2.z; pacc[rr].w += a4.z * w2.w;
                pacc[rr].x += a4.w * w3.x; pacc[rr].y += a4.w * w3.y;
                pacc[rr].z += a4.w * w3.z; pacc[rr].w += a4.w * w3.w;
            }
        }
        const int nt = blockIdx.y;
        #pragma unroll
        for (int rr = 0; rr < 8; rr++) {
            int b = m0 + w * 8 + rr;
            *(float4*)&g_part[((size_t)nt * BB + b) * CC + lane * 4] = pacc[rr];
        }
    }
}

// ---------------------------------------------------------------------------
// Kernel 2 (per step): reduce 8 projection partials + bias -> logits;
// stage logits [B,T,C]; argmax (first-max) -> g_tok and tokens [B,T].
// grid 256 CTAs x 256 threads; one warp per batch row.
// ---------------------------------------------------------------------------
__global__ __launch_bounds__(256)
void finalize(const float* __restrict__ bp, float* __restrict__ out, int t) {
    const int tid = threadIdx.x;
    const int w = tid >> 5, lane = tid & 31;
    const int b = blockIdx.x * 8 + w;

    float4 s = make_float4(0.f, 0.f, 0.f, 0.f);
    #pragma unroll
    for (int p = 0; p < 8; p++) {
        float4 v = *(const float4*)&g_part[((size_t)p * BB + b) * CC + lane * 4];
        s.x += v.x; s.y += v.y; s.z += v.z; s.w += v.w;
    }
    const float4 bpv = *(const float4*)&bp[lane * 4];
    s.x += bpv.x; s.y += bpv.y; s.z += bpv.z; s.w += bpv.w;

    *(float4*)&g_log[((size_t)b * TT + t) * CC + lane * 4] = s;

    // argmax, first-max semantics
    float vv[4] = {s.x, s.y, s.z, s.w};
    float bv = -3.402823466e38f;
    int bi = 0;
    #pragma unroll
    for (int j = 0; j < 4; j++) {
        if (vv[j] > bv) { bv = vv[j]; bi = lane * 4 + j; }
    }
    #pragma unroll
    for (int off = 16; off; off >>= 1) {
        float ov = __shfl_xor_sync(0xffffffffu, bv, off);
        int   oi = __shfl_xor_sync(0xffffffffu, bi, off);
        if (ov > bv || (ov == bv && oi < bi)) { bv = ov; bi = oi; }
    }
    if (lane == 0) {
        g_tok[b] = bi;
        float* out_tok = out + (size_t)BB * CC * TT;
        out_tok[(size_t)b * TT + t] = (float)bi;
    }
}

// ---------------------------------------------------------------------------
// Kernel 3 (once, at end): transpose staged logits [B,T,C] -> d_out [B,C,T].
// ---------------------------------------------------------------------------
__global__ __launch_bounds__(256)
void transp(float* __restrict__ out) {
    __shared__ float tile[32][33];
    const int b  = blockIdx.z;
    const int t0 = blockIdx.x * 32, c0 = blockIdx.y * 32;
    const int tx = threadIdx.x, ty = threadIdx.y;

    #pragma unroll
    for (int i = ty; i < 32; i += 8) {
        int t = t0 + i;
        if (t < TT)
            tile[i][tx] = g_log[((size_t)b * TT + t) * CC + c0 + tx];
    }
    __syncthreads();
    #pragma unroll
    for (int i = ty; i < 32; i += 8) {
        int c = c0 + i;
        int t = t0 + tx;
        if (t < TT)
            out[((size_t)b * CC + c) * TT + t] = tile[tx][i];
    }
}

// ---------------------------------------------------------------------------
// kernel_launch: graph-capturable, no allocation.
// Inputs (metadata order): feat, W_ih, W_hh, b_ih, b_hh, W_proj, b_proj, embed
// Output: logits [B,C,T] float32 then tokens [B,T] as float32.
// ---------------------------------------------------------------------------
extern "C" void kernel_launch(void* const* d_in, const int* in_sizes, int n_in,
                              void* d_out, int out_size) {
    const float* feat  = (const float*)d_in[0];
    const float* Wih   = (const float*)d_in[1];
    const float* Whh   = (const float*)d_in[2];
    const float* bih   = (const float*)d_in[3];
    const float* bhh   = (const float*)d_in[4];
    const float* Wp    = (const float*)d_in[5];
    const float* bp    = (const float*)d_in[6];
    const float* embed = (const float*)d_in[7];
    float* out = (float*)d_out;

    build_tab<<<dim3(CC + 1, G3 / 256), 256>>>(Wih, bih, bhh, embed);
    build_wpt<<<DD * CC / 256, 256>>>(Wp);
    init_tok<<<(BB + 255) / 256, 256>>>();

    for (int t = 0; t < TT; t++) {
        step_h<<<dim3(BB / 64, DD / 64), 256>>>(feat, Whh, bhh, t);
        finalize<<<BB / 8, 256>>>(bp, out, t);
    }

    transp<<<dim3((TT + 31) / 32, CC / 32, BB), dim3(32, 8)>>>(out);
}